// round 11
// baseline (speedup 1.0000x reference)
#include <cuda_runtime.h>
#include <cstdint>

#define BATCH  4
#define N_PTS  16384
#define N_SAMP 1024
#define K_NEI  32
#define C_FEAT 128
#define CL     8               // cluster size (CTAs per batch)
#define TPB    128
#define NWARP  (TPB / 32)      // 4 warps per CTA
#define PPT    16              // N_PTS / (CL*TPB)
#define FULL   0xffffffffu
#define TX_BYTES (CL * 16u)    // 8 producers (one per CTA) x one v4 (16B)

// scratch: neighbor indices (device global -> no allocation)
__device__ int g_nidx[BATCH * N_SAMP * K_NEI];

// ---------------- threefry2x32 (JAX-compatible, both output words) ----------------
__device__ __forceinline__ uint32_t rotl32(uint32_t x, int r) {
    return (x << r) | (x >> (32 - r));
}

__device__ __forceinline__ void threefry2x32(uint32_t k0, uint32_t k1,
                                             uint32_t x0, uint32_t x1,
                                             uint32_t& o0, uint32_t& o1) {
    uint32_t ks2 = k0 ^ k1 ^ 0x1BD11BDAu;
    x0 += k0; x1 += k1;
#define TF_RND(r) { x0 += x1; x1 = rotl32(x1, (r)); x1 ^= x0; }
    TF_RND(13) TF_RND(15) TF_RND(26) TF_RND(6)   x0 += k1;  x1 += ks2 + 1u;
    TF_RND(17) TF_RND(29) TF_RND(16) TF_RND(24)  x0 += ks2; x1 += k0 + 2u;
    TF_RND(13) TF_RND(15) TF_RND(26) TF_RND(6)   x0 += k0;  x1 += k1 + 3u;
    TF_RND(17) TF_RND(29) TF_RND(16) TF_RND(24)  x0 += k1;  x1 += ks2 + 4u;
    TF_RND(13) TF_RND(15) TF_RND(26) TF_RND(6)   x0 += ks2; x1 += k0 + 5u;
#undef TF_RND
    o0 = x0; o1 = x1;
}

// start index for batch b (JAX threefry_partitionable=True path):
//   k1,k2 = split(key(42)); bits_b = o0^o1 of tf2x32(k2,(0,b)); start = bits & 16383
__device__ __forceinline__ int jax_start_idx(int b) {
    uint32_t k2a, k2b;
    threefry2x32(0u, 42u, 0u, 1u, k2a, k2b);
    uint32_t o0, o1;
    threefry2x32(k2a, k2b, 0u, (uint32_t)b, o0, o1);
    return (int)((o0 ^ o1) & (uint32_t)(N_PTS - 1));
}

// ---------------- cluster DSMEM / mbarrier helpers ----------------
__device__ __forceinline__ uint32_t mapa_peer(uint32_t laddr, uint32_t peer) {
    uint32_t r;
    asm volatile("mapa.shared::cluster.u32 %0, %1, %2;" : "=r"(r) : "r"(laddr), "r"(peer));
    return r;
}
// fused store+signal with pre-resolved remote addresses
__device__ __forceinline__ void st_async_raw_v4(uint32_t raddr, uint32_t rmbar,
                                                uint32_t a, uint32_t b,
                                                uint32_t c, uint32_t d) {
    asm volatile("st.async.shared::cluster.mbarrier::complete_tx::bytes.v4.b32 "
                 "[%0], {%1,%2,%3,%4}, [%5];"
                 :: "r"(raddr), "r"(a), "r"(b), "r"(c), "r"(d), "r"(rmbar) : "memory");
}
__device__ __forceinline__ void mbar_expect_tx(uint32_t mbar, uint32_t bytes) {
    asm volatile("mbarrier.arrive.expect_tx.shared.b64 _, [%0], %1;"
                 :: "r"(mbar), "r"(bytes) : "memory");
}
__device__ __forceinline__ void mbar_wait(uint32_t mbar, uint32_t phase) {
    uint32_t done = 0;
    while (!done) {
        asm volatile(
            "{\n\t.reg .pred p;\n\t"
            "mbarrier.try_wait.parity.acquire.cluster.shared::cta.b64 p, [%1], %2, 0x989680;\n\t"
            "selp.b32 %0, 1, 0, p;\n\t}"
            : "=r"(done) : "r"(mbar), "r"(phase) : "memory");
    }
}

// ---------------- FPS: one 8-CTA cluster per batch ----------------
// BLOCKED mapping: thread t of CTA rank owns indices
//   [rank*2048 + t*PPT, rank*2048 + (t+1)*PPT)
// so index order == (rank, warp, lane, j) order -> every tie-break is
// ffs(ballot)/lowest-slot, and no index ever needs to be transported.
__global__ void __cluster_dims__(CL, 1, 1) __launch_bounds__(TPB, 1)
fps_kernel(const float* __restrict__ xyz, float* __restrict__ out_xyz) {
    const int b = blockIdx.x / CL;
    uint32_t rank;
    asm("mov.u32 %0, %%cluster_ctarank;" : "=r"(rank));
    const float* __restrict__ X = xyz + (size_t)b * N_PTS * 3;
    const int t = threadIdx.x;
    const int lane = t & 31, w = t >> 5;
    const int tbase = (int)rank * (TPB * PPT) + t * PPT;

    // register-resident points + running min distance
    float px[PPT], py[PPT], pz[PPT], md[PPT];
#pragma unroll
    for (int j = 0; j < PPT; j++) {
        const float* a = X + 3 * (tbase + j);
        px[j] = a[0];
        py[j] = a[1];
        pz[j] = a[2];
        md[j] = __int_as_float(0x7f800000);  // +inf
    }

    // local per-warp winners (4 slots), cross-CTA candidates (8 slots, dbl-buf)
    __shared__ uint4 s_w[NWARP];
    __shared__ uint4 s_q[2][CL];
    __shared__ unsigned long long s_mbar[2];

    if (t == 0) {
        asm volatile("mbarrier.init.shared.b64 [%0], %1;"
                     :: "r"((uint32_t)__cvta_generic_to_shared(&s_mbar[0])), "r"(1) : "memory");
        asm volatile("mbarrier.init.shared.b64 [%0], %1;"
                     :: "r"((uint32_t)__cvta_generic_to_shared(&s_mbar[1])), "r"(1) : "memory");
    }
    __syncthreads();
    asm volatile("barrier.cluster.arrive.aligned;" ::: "memory");
    asm volatile("barrier.cluster.wait.aligned;" ::: "memory");

    // pre-resolve remote slot/mbar addresses (CTA slot == rank), both buffers
    uint32_t rs0[CL], rs1[CL], rm0[CL], rm1[CL];
    {
        uint32_t a0 = (uint32_t)__cvta_generic_to_shared(&s_q[0][rank]);
        uint32_t a1 = (uint32_t)__cvta_generic_to_shared(&s_q[1][rank]);
        uint32_t m0 = (uint32_t)__cvta_generic_to_shared(&s_mbar[0]);
        uint32_t m1 = (uint32_t)__cvta_generic_to_shared(&s_mbar[1]);
#pragma unroll
        for (int p = 0; p < CL; p++) {
            rs0[p] = mapa_peer(a0, (uint32_t)p);
            rs1[p] = mapa_peer(a1, (uint32_t)p);
            rm0[p] = mapa_peer(m0, (uint32_t)p);
            rm1[p] = mapa_peer(m1, (uint32_t)p);
        }
    }

    int cur = jax_start_idx(b);
    float qx = X[3 * cur + 0], qy = X[3 * cur + 1], qz = X[3 * cur + 2];

    for (int s = 0; ; s++) {
        if (rank == 0 && t == 0) {
            float* o = out_xyz + ((size_t)b * N_SAMP + s) * 3;
            o[0] = qx; o[1] = qy; o[2] = qz;
        }
        if (s == N_SAMP - 1) break;

        const int buf = s & 1;
        // arm this phase's mbar (arrival count 1 = this arrive.expect_tx, so the
        // phase cannot flip before this post even if producer bytes land first)
        if (t == 0)
            mbar_expect_tx((uint32_t)__cvta_generic_to_shared(&s_mbar[buf]), TX_BYTES);

        // ---- thread-local update: all 16 distances independent (full ILP).
        //      EXACT: no FMA contraction, left-assoc sum, IEEE fminf ----
        float m[PPT];
#pragma unroll
        for (int j = 0; j < PPT; j++) {
            float dx = __fsub_rn(px[j], qx);
            float dy = __fsub_rn(py[j], qy);
            float dz = __fsub_rn(pz[j], qz);
            float d2 = __fadd_rn(__fadd_rn(__fmul_rn(dx, dx), __fmul_rn(dy, dy)),
                                 __fmul_rn(dz, dz));
            float mm = fminf(md[j], d2);
            md[j] = mm;
            m[j] = mm;
        }
        // ---- depth-4 adjacent-pair argmax tree (left-priority => smallest j
        //      on ties, i.e. exact argmax-first). values finite non-negative. ----
        float tv[8], tx[8], ty[8], tz[8];
#pragma unroll
        for (int k = 0; k < 8; k++) {
            bool g = m[2 * k + 1] > m[2 * k];
            tv[k] = g ? m[2 * k + 1]  : m[2 * k];
            tx[k] = g ? px[2 * k + 1] : px[2 * k];
            ty[k] = g ? py[2 * k + 1] : py[2 * k];
            tz[k] = g ? pz[2 * k + 1] : pz[2 * k];
        }
#pragma unroll
        for (int n = 4; n >= 1; n >>= 1) {
#pragma unroll
            for (int k = 0; k < n; k++) {
                bool g = tv[2 * k + 1] > tv[2 * k];
                tv[k] = g ? tv[2 * k + 1] : tv[2 * k];
                tx[k] = g ? tx[2 * k + 1] : tx[2 * k];
                ty[k] = g ? ty[2 * k + 1] : ty[2 * k];
                tz[k] = g ? tz[2 * k + 1] : tz[2 * k];
            }
        }
        const uint32_t bu = __float_as_uint(tv[0]);  // >=0: IEEE order == u32 order

        // ---- stage A: warp winner -> local smem slot (warp order==index order) ----
        uint32_t wm = __reduce_max_sync(FULL, bu);
        uint32_t mk = __ballot_sync(FULL, bu == wm);
        if (lane == __ffs(mk) - 1) {
            s_w[w] = make_uint4(wm, __float_as_uint(tx[0]),
                                    __float_as_uint(ty[0]), __float_as_uint(tz[0]));
        }
        __syncthreads();

        // ---- stage B (warp 0 only): reduce 4 slots, single producer per CTA ----
        if (w == 0) {
            uint4 wv = (lane < NWARP) ? s_w[lane]
                                      : make_uint4(0u, 0u, 0u, 0u);
            uint32_t cm = __reduce_max_sync(FULL, wv.x);
            uint32_t mkc = __ballot_sync(FULL, wv.x == cm);
            if (lane == __ffs(mkc) - 1) {   // lowest slot == smallest index
                if (buf) {
#pragma unroll
                    for (int p = 0; p < CL; p++)
                        st_async_raw_v4(rs1[p], rm1[p], cm, wv.y, wv.z, wv.w);
                } else {
#pragma unroll
                    for (int p = 0; p < CL; p++)
                        st_async_raw_v4(rs0[p], rm0[p], cm, wv.y, wv.z, wv.w);
                }
            }
        }

        // ---- all warps: wait for 8 CTA candidates, reduce; lowest winning slot
        //      == smallest index (slot == rank, rank order == index order) ----
        mbar_wait((uint32_t)__cvta_generic_to_shared(&s_mbar[buf]), (uint32_t)((s >> 1) & 1));
        uint4 dv = (lane < CL) ? s_q[buf][lane] : make_uint4(0u, 0u, 0u, 0u);
        uint32_t gm = __reduce_max_sync(FULL, dv.x);
        uint32_t mk2 = __ballot_sync(FULL, dv.x == gm);
        int ws = __ffs(mk2) - 1;
        qx = __uint_as_float(__shfl_sync(FULL, dv.y, ws));
        qy = __uint_as_float(__shfl_sync(FULL, dv.z, ws));
        qz = __uint_as_float(__shfl_sync(FULL, dv.w, ws));
    }

    // drain: no CTA exits while peers may still target its smem
    asm volatile("barrier.cluster.arrive.aligned;" ::: "memory");
    asm volatile("barrier.cluster.wait.aligned;" ::: "memory");
}

// ---------------- ball query: one warp per query, first-32-by-index ----------------
__global__ void ball_kernel(const float* __restrict__ xyz,
                            const float* __restrict__ samp) {
    const int warp = (int)((blockIdx.x * blockDim.x + threadIdx.x) >> 5);
    const int lane = threadIdx.x & 31;
    if (warp >= BATCH * N_SAMP) return;
    const int b = warp >> 10;  // 1024 samples per batch
    const float* q = samp + (size_t)warp * 3;
    const float qx = q[0], qy = q[1], qz = q[2];
    const float* __restrict__ X = xyz + (size_t)b * N_PTS * 3;
    int* out = g_nidx + (size_t)warp * K_NEI;

    out[lane] = -1;  // default padding
    int cnt = 0;
    const float R2 = 0.04f;  // f32(0.04): matches JAX weak-typed radius*radius
    for (int base = 0; base < N_PTS && cnt < K_NEI; base += 32) {
        const int i = base + lane;
        float dx = __fsub_rn(qx, X[3 * i + 0]);
        float dy = __fsub_rn(qy, X[3 * i + 1]);
        float dz = __fsub_rn(qz, X[3 * i + 2]);
        float d2 = __fadd_rn(__fadd_rn(__fmul_rn(dx, dx), __fmul_rn(dy, dy)),
                             __fmul_rn(dz, dz));
        const bool in = d2 < R2;
        const unsigned m = __ballot_sync(0xffffffffu, in);
        if (in) {
            int r = cnt + __popc(m & ((1u << lane) - 1u));
            if (r < K_NEI) out[r] = i;
        }
        cnt += __popc(m);
    }
}

// ---------------- gather: one warp per (b,s,k) row, 128 floats ----------------
__global__ void gather_kernel(const float* __restrict__ feat,
                              float* __restrict__ out_feat) {
    const int warp = (int)((blockIdx.x * blockDim.x + threadIdx.x) >> 5);
    const int lane = threadIdx.x & 31;
    if (warp >= BATCH * N_SAMP * K_NEI) return;
    const int b = warp >> 15;  // 1024*32 rows per batch
    int idx = g_nidx[warp];
    int row = (idx < 0) ? N_SAMP : idx;  // -1 -> feat[:, 1024, :]
    const float4* src = (const float4*)(feat + ((size_t)b * N_PTS + row) * C_FEAT);
    float4* dst = (float4*)(out_feat + (size_t)warp * C_FEAT);
    dst[lane] = src[lane];
}

extern "C" void kernel_launch(void* const* d_in, const int* in_sizes, int n_in,
                              void* d_out, int out_size) {
    const float* xyz  = (const float*)d_in[0];
    const float* feat = (const float*)d_in[1];
    if (n_in >= 2 && in_sizes[0] != BATCH * N_PTS * 3) {  // defensive: identify by size
        xyz  = (const float*)d_in[1];
        feat = (const float*)d_in[0];
    }
    float* out = (float*)d_out;
    float* out_feat = out + (size_t)BATCH * N_SAMP * 3;

    fps_kernel<<<BATCH * CL, TPB>>>(xyz, out);

    const int ball_threads = BATCH * N_SAMP * 32;            // one warp/query
    ball_kernel<<<ball_threads / 256, 256>>>(xyz, out);

    const int gath_threads = BATCH * N_SAMP * K_NEI * 32;    // one warp/row
    gather_kernel<<<gath_threads / 256, 256>>>(feat, out_feat);
}

// round 12
// speedup vs baseline: 1.1605x; 1.1605x over previous
#include <cuda_runtime.h>
#include <cstdint>

#define BATCH  4
#define N_PTS  16384
#define N_SAMP 1024
#define K_NEI  32
#define C_FEAT 128
#define CL     8               // cluster size (CTAs per batch)
#define TPB    128
#define NWARP  (TPB / 32)      // 4 warps per CTA
#define PPT    16              // N_PTS / (CL*TPB)
#define NPAIR  (PPT / 2)
#define NSLOT  (CL * NWARP)    // 32 cluster-wide warp candidates (== warp size)
#define FULL   0xffffffffu
#define TX_BYTES (NSLOT * 16u) // 32 producers x one v4 (16B)

// scratch: neighbor indices (device global -> no allocation)
__device__ int g_nidx[BATCH * N_SAMP * K_NEI];

// ---------------- f32x2 packed helpers (per-lane IEEE .rn == scalar; proven
// bit-exact on this bench in R8: rel_err == 0.0) ----------------
__device__ __forceinline__ uint64_t pack2(float lo, float hi) {
    uint64_t r;
    asm("mov.b64 %0, {%1, %2};" : "=l"(r) : "f"(lo), "f"(hi));
    return r;
}
__device__ __forceinline__ void unpack2(uint64_t v, float& lo, float& hi) {
    asm("mov.b64 {%0, %1}, %2;" : "=f"(lo), "=f"(hi) : "l"(v));
}
__device__ __forceinline__ uint64_t add2(uint64_t a, uint64_t b) {
    uint64_t r;
    asm("add.rn.f32x2 %0, %1, %2;" : "=l"(r) : "l"(a), "l"(b));
    return r;
}
__device__ __forceinline__ uint64_t mul2(uint64_t a, uint64_t b) {
    uint64_t r;
    asm("mul.rn.f32x2 %0, %1, %2;" : "=l"(r) : "l"(a), "l"(b));
    return r;
}

// ---------------- threefry2x32 (JAX-compatible, both output words) ----------------
__device__ __forceinline__ uint32_t rotl32(uint32_t x, int r) {
    return (x << r) | (x >> (32 - r));
}

__device__ __forceinline__ void threefry2x32(uint32_t k0, uint32_t k1,
                                             uint32_t x0, uint32_t x1,
                                             uint32_t& o0, uint32_t& o1) {
    uint32_t ks2 = k0 ^ k1 ^ 0x1BD11BDAu;
    x0 += k0; x1 += k1;
#define TF_RND(r) { x0 += x1; x1 = rotl32(x1, (r)); x1 ^= x0; }
    TF_RND(13) TF_RND(15) TF_RND(26) TF_RND(6)   x0 += k1;  x1 += ks2 + 1u;
    TF_RND(17) TF_RND(29) TF_RND(16) TF_RND(24)  x0 += ks2; x1 += k0 + 2u;
    TF_RND(13) TF_RND(15) TF_RND(26) TF_RND(6)   x0 += k0;  x1 += k1 + 3u;
    TF_RND(17) TF_RND(29) TF_RND(16) TF_RND(24)  x0 += k1;  x1 += ks2 + 4u;
    TF_RND(13) TF_RND(15) TF_RND(26) TF_RND(6)   x0 += ks2; x1 += k0 + 5u;
#undef TF_RND
    o0 = x0; o1 = x1;
}

// start index for batch b (JAX threefry_partitionable=True path):
//   k1,k2 = split(key(42)); bits_b = o0^o1 of tf2x32(k2,(0,b)); start = bits & 16383
__device__ __forceinline__ int jax_start_idx(int b) {
    uint32_t k2a, k2b;
    threefry2x32(0u, 42u, 0u, 1u, k2a, k2b);
    uint32_t o0, o1;
    threefry2x32(k2a, k2b, 0u, (uint32_t)b, o0, o1);
    return (int)((o0 ^ o1) & (uint32_t)(N_PTS - 1));
}

// ---------------- cluster DSMEM / mbarrier helpers ----------------
__device__ __forceinline__ uint32_t mapa_peer(uint32_t laddr, uint32_t peer) {
    uint32_t r;
    asm volatile("mapa.shared::cluster.u32 %0, %1, %2;" : "=r"(r) : "r"(laddr), "r"(peer));
    return r;
}
// fused store+signal with pre-resolved remote addresses
__device__ __forceinline__ void st_async_raw_v4(uint32_t raddr, uint32_t rmbar,
                                                uint32_t a, uint32_t b,
                                                uint32_t c, uint32_t d) {
    asm volatile("st.async.shared::cluster.mbarrier::complete_tx::bytes.v4.b32 "
                 "[%0], {%1,%2,%3,%4}, [%5];"
                 :: "r"(raddr), "r"(a), "r"(b), "r"(c), "r"(d), "r"(rmbar) : "memory");
}
__device__ __forceinline__ void mbar_expect_tx(uint32_t mbar, uint32_t bytes) {
    asm volatile("mbarrier.arrive.expect_tx.shared.b64 _, [%0], %1;"
                 :: "r"(mbar), "r"(bytes) : "memory");
}
__device__ __forceinline__ void mbar_wait(uint32_t mbar, uint32_t phase) {
    uint32_t done = 0;
    while (!done) {
        asm volatile(
            "{\n\t.reg .pred p;\n\t"
            "mbarrier.try_wait.parity.acquire.cluster.shared::cta.b64 p, [%1], %2, 0x989680;\n\t"
            "selp.b32 %0, 1, 0, p;\n\t}"
            : "=r"(done) : "r"(mbar), "r"(phase) : "memory");
    }
}

// ---------------- FPS: one 8-CTA cluster per batch ----------------
// BLOCKED mapping: thread t of CTA rank owns indices
//   [rank*2048 + t*PPT, rank*2048 + (t+1)*PPT)
// so index order == (slot, lane, j) order -> every tie-break is ffs(ballot),
// and no index ever needs to be reduced or transported.
__global__ void __cluster_dims__(CL, 1, 1) __launch_bounds__(TPB, 1)
fps_kernel(const float* __restrict__ xyz, float* __restrict__ out_xyz) {
    const int b = blockIdx.x / CL;
    uint32_t rank;
    asm("mov.u32 %0, %%cluster_ctarank;" : "=r"(rank));
    const float* __restrict__ X = xyz + (size_t)b * N_PTS * 3;
    const int t = threadIdx.x;
    const int lane = t & 31, w = t >> 5;
    const int tbase = (int)rank * (TPB * PPT) + t * PPT;

    // points: scalar copies (for the select tree) + packed pairs (for distance)
    float px[PPT], py[PPT], pz[PPT], md[PPT];
#pragma unroll
    for (int j = 0; j < PPT; j++) {
        const float* a = X + 3 * (tbase + j);
        px[j] = a[0];
        py[j] = a[1];
        pz[j] = a[2];
        md[j] = __int_as_float(0x7f800000);  // +inf
    }
    uint64_t px2[NPAIR], py2[NPAIR], pz2[NPAIR];
#pragma unroll
    for (int p = 0; p < NPAIR; p++) {
        px2[p] = pack2(px[2 * p], px[2 * p + 1]);
        py2[p] = pack2(py[2 * p], py[2 * p + 1]);
        pz2[p] = pack2(pz[2 * p], pz[2 * p + 1]);
    }

    // cluster-wide candidates: one v4 {dist,x,y,z} per slot, double-buffered
    __shared__ uint4 s_q[2][NSLOT];
    __shared__ unsigned long long s_mbar[2];

    if (t == 0) {
        asm volatile("mbarrier.init.shared.b64 [%0], %1;"
                     :: "r"((uint32_t)__cvta_generic_to_shared(&s_mbar[0])), "r"(1) : "memory");
        asm volatile("mbarrier.init.shared.b64 [%0], %1;"
                     :: "r"((uint32_t)__cvta_generic_to_shared(&s_mbar[1])), "r"(1) : "memory");
    }
    __syncthreads();
    asm volatile("barrier.cluster.arrive.aligned;" ::: "memory");
    asm volatile("barrier.cluster.wait.aligned;" ::: "memory");

    // pre-resolve remote slot/mbar addresses for my warp's slot, both buffers
    const int myslot = (int)rank * NWARP + w;
    uint32_t rs0[CL], rs1[CL], rm0[CL], rm1[CL];
    {
        uint32_t a0 = (uint32_t)__cvta_generic_to_shared(&s_q[0][myslot]);
        uint32_t a1 = (uint32_t)__cvta_generic_to_shared(&s_q[1][myslot]);
        uint32_t m0 = (uint32_t)__cvta_generic_to_shared(&s_mbar[0]);
        uint32_t m1 = (uint32_t)__cvta_generic_to_shared(&s_mbar[1]);
#pragma unroll
        for (int p = 0; p < CL; p++) {
            rs0[p] = mapa_peer(a0, (uint32_t)p);
            rs1[p] = mapa_peer(a1, (uint32_t)p);
            rm0[p] = mapa_peer(m0, (uint32_t)p);
            rm1[p] = mapa_peer(m1, (uint32_t)p);
        }
    }

    int cur = jax_start_idx(b);
    float qx = X[3 * cur + 0], qy = X[3 * cur + 1], qz = X[3 * cur + 2];

    for (int s = 0; ; s++) {
        if (rank == 0 && t == 0) {
            float* o = out_xyz + ((size_t)b * N_SAMP + s) * 3;
            o[0] = qx; o[1] = qy; o[2] = qz;
        }
        if (s == N_SAMP - 1) break;

        const int buf = s & 1;
        // arm this phase's mbar (arrival count 1 = this arrive.expect_tx, so the
        // phase cannot flip before this post even if producer bytes land first)
        if (t == 0)
            mbar_expect_tx((uint32_t)__cvta_generic_to_shared(&s_mbar[buf]), TX_BYTES);

        // ---- distance stage: packed f32x2, 2 points/op (EXACT per lane:
        //      a-b == a+(-b), .rn mul/add, left-assoc ((x2+y2)+z2)) ----
        const uint64_t nqx2 = pack2(-qx, -qx);
        const uint64_t nqy2 = pack2(-qy, -qy);
        const uint64_t nqz2 = pack2(-qz, -qz);
        float m[PPT];
#pragma unroll
        for (int p = 0; p < NPAIR; p++) {
            uint64_t dx2 = add2(px2[p], nqx2);
            uint64_t dy2 = add2(py2[p], nqy2);
            uint64_t dz2 = add2(pz2[p], nqz2);
            uint64_t d2p = add2(add2(mul2(dx2, dx2), mul2(dy2, dy2)),
                                mul2(dz2, dz2));
            float dlo, dhi;
            unpack2(d2p, dlo, dhi);
            float m0v = fminf(md[2 * p],     dlo);
            float m1v = fminf(md[2 * p + 1], dhi);
            md[2 * p]     = m0v;
            md[2 * p + 1] = m1v;
            m[2 * p]     = m0v;
            m[2 * p + 1] = m1v;
        }
        // ---- depth-4 adjacent-pair argmax tree (left-priority => smallest j
        //      on ties, i.e. exact argmax-first). values finite non-negative. ----
        float tv[8], tx[8], ty[8], tz[8];
#pragma unroll
        for (int k = 0; k < 8; k++) {
            bool g = m[2 * k + 1] > m[2 * k];
            tv[k] = g ? m[2 * k + 1]  : m[2 * k];
            tx[k] = g ? px[2 * k + 1] : px[2 * k];
            ty[k] = g ? py[2 * k + 1] : py[2 * k];
            tz[k] = g ? pz[2 * k + 1] : pz[2 * k];
        }
#pragma unroll
        for (int n = 4; n >= 1; n >>= 1) {
#pragma unroll
            for (int k = 0; k < n; k++) {
                bool g = tv[2 * k + 1] > tv[2 * k];
                tv[k] = g ? tv[2 * k + 1] : tv[2 * k];
                tx[k] = g ? tx[2 * k + 1] : tx[2 * k];
                ty[k] = g ? ty[2 * k + 1] : ty[2 * k];
                tz[k] = g ? tz[2 * k + 1] : tz[2 * k];
            }
        }
        const uint32_t bu = __float_as_uint(tv[0]);  // >=0: IEEE order == u32 order

        // ---- warp argmax; winning lane (lowest on ties == smallest index)
        //      broadcasts its own candidate to all 8 CTAs directly ----
        uint32_t wm = __reduce_max_sync(FULL, bu);
        uint32_t mk = __ballot_sync(FULL, bu == wm);
        if (lane == __ffs(mk) - 1) {
            uint32_t cx = __float_as_uint(tx[0]);
            uint32_t cy = __float_as_uint(ty[0]);
            uint32_t cz = __float_as_uint(tz[0]);
            if (buf) {
#pragma unroll
                for (int p = 0; p < CL; p++)
                    st_async_raw_v4(rs1[p], rm1[p], wm, cx, cy, cz);
            } else {
#pragma unroll
                for (int p = 0; p < CL; p++)
                    st_async_raw_v4(rs0[p], rm0[p], wm, cx, cy, cz);
            }
        }

        // ---- all warps: wait, 1 slot/lane; lowest winning slot == smallest index ----
        mbar_wait((uint32_t)__cvta_generic_to_shared(&s_mbar[buf]), (uint32_t)((s >> 1) & 1));
        uint4 dv = s_q[buf][lane];
        uint32_t gm = __reduce_max_sync(FULL, dv.x);
        uint32_t mk2 = __ballot_sync(FULL, dv.x == gm);
        int ws = __ffs(mk2) - 1;
        qx = __uint_as_float(__shfl_sync(FULL, dv.y, ws));
        qy = __uint_as_float(__shfl_sync(FULL, dv.z, ws));
        qz = __uint_as_float(__shfl_sync(FULL, dv.w, ws));
    }

    // drain: no CTA exits while peers may still target its smem
    asm volatile("barrier.cluster.arrive.aligned;" ::: "memory");
    asm volatile("barrier.cluster.wait.aligned;" ::: "memory");
}

// ---------------- ball query: one warp per query, first-32-by-index ----------------
__global__ void ball_kernel(const float* __restrict__ xyz,
                            const float* __restrict__ samp) {
    const int warp = (int)((blockIdx.x * blockDim.x + threadIdx.x) >> 5);
    const int lane = threadIdx.x & 31;
    if (warp >= BATCH * N_SAMP) return;
    const int b = warp >> 10;  // 1024 samples per batch
    const float* q = samp + (size_t)warp * 3;
    const float qx = q[0], qy = q[1], qz = q[2];
    const float* __restrict__ X = xyz + (size_t)b * N_PTS * 3;
    int* out = g_nidx + (size_t)warp * K_NEI;

    out[lane] = -1;  // default padding
    int cnt = 0;
    const float R2 = 0.04f;  // f32(0.04): matches JAX weak-typed radius*radius
    for (int base = 0; base < N_PTS && cnt < K_NEI; base += 32) {
        const int i = base + lane;
        float dx = __fsub_rn(qx, X[3 * i + 0]);
        float dy = __fsub_rn(qy, X[3 * i + 1]);
        float dz = __fsub_rn(qz, X[3 * i + 2]);
        float d2 = __fadd_rn(__fadd_rn(__fmul_rn(dx, dx), __fmul_rn(dy, dy)),
                             __fmul_rn(dz, dz));
        const bool in = d2 < R2;
        const unsigned m = __ballot_sync(0xffffffffu, in);
        if (in) {
            int r = cnt + __popc(m & ((1u << lane) - 1u));
            if (r < K_NEI) out[r] = i;
        }
        cnt += __popc(m);
    }
}

// ---------------- gather: one warp per (b,s,k) row, 128 floats ----------------
__global__ void gather_kernel(const float* __restrict__ feat,
                              float* __restrict__ out_feat) {
    const int warp = (int)((blockIdx.x * blockDim.x + threadIdx.x) >> 5);
    const int lane = threadIdx.x & 31;
    if (warp >= BATCH * N_SAMP * K_NEI) return;
    const int b = warp >> 15;  // 1024*32 rows per batch
    int idx = g_nidx[warp];
    int row = (idx < 0) ? N_SAMP : idx;  // -1 -> feat[:, 1024, :]
    const float4* src = (const float4*)(feat + ((size_t)b * N_PTS + row) * C_FEAT);
    float4* dst = (float4*)(out_feat + (size_t)warp * C_FEAT);
    dst[lane] = src[lane];
}

extern "C" void kernel_launch(void* const* d_in, const int* in_sizes, int n_in,
                              void* d_out, int out_size) {
    const float* xyz  = (const float*)d_in[0];
    const float* feat = (const float*)d_in[1];
    if (n_in >= 2 && in_sizes[0] != BATCH * N_PTS * 3) {  // defensive: identify by size
        xyz  = (const float*)d_in[1];
        feat = (const float*)d_in[0];
    }
    float* out = (float*)d_out;
    float* out_feat = out + (size_t)BATCH * N_SAMP * 3;

    fps_kernel<<<BATCH * CL, TPB>>>(xyz, out);

    const int ball_threads = BATCH * N_SAMP * 32;            // one warp/query
    ball_kernel<<<ball_threads / 256, 256>>>(xyz, out);

    const int gath_threads = BATCH * N_SAMP * K_NEI * 32;    // one warp/row
    gather_kernel<<<gath_threads / 256, 256>>>(feat, out_feat);
}

// round 13
// speedup vs baseline: 1.2075x; 1.0404x over previous
#include <cuda_runtime.h>
#include <cstdint>

#define BATCH  4
#define N_PTS  16384
#define N_SAMP 1024
#define K_NEI  32
#define C_FEAT 128
#define CL     8                 // cluster size (CTAs per batch)
#define TPB    256               // warps 0-3: ball/gather, warps 4-7: FPS
#define NWARP_FPS 4
#define PPT    16                // 2048 pts per CTA / 128 fps threads
#define NPAIR  (PPT / 2)
#define NSLOT  (CL * NWARP_FPS)  // 32 cluster-wide warp candidates
#define FULL   0xffffffffu
#define TX_BYTES (NSLOT * 16u)   // 32 producers x one v4 (16B)

// ---------------- f32x2 packed helpers (per-lane IEEE .rn == scalar; proven
// bit-exact on this bench: rel_err == 0.0) ----------------
__device__ __forceinline__ uint64_t pack2(float lo, float hi) {
    uint64_t r;
    asm("mov.b64 %0, {%1, %2};" : "=l"(r) : "f"(lo), "f"(hi));
    return r;
}
__device__ __forceinline__ void unpack2(uint64_t v, float& lo, float& hi) {
    asm("mov.b64 {%0, %1}, %2;" : "=f"(lo), "=f"(hi) : "l"(v));
}
__device__ __forceinline__ uint64_t add2(uint64_t a, uint64_t b) {
    uint64_t r;
    asm("add.rn.f32x2 %0, %1, %2;" : "=l"(r) : "l"(a), "l"(b));
    return r;
}
__device__ __forceinline__ uint64_t mul2(uint64_t a, uint64_t b) {
    uint64_t r;
    asm("mul.rn.f32x2 %0, %1, %2;" : "=l"(r) : "l"(a), "l"(b));
    return r;
}

// ---------------- threefry2x32 (JAX-compatible) ----------------
__device__ __forceinline__ uint32_t rotl32(uint32_t x, int r) {
    return (x << r) | (x >> (32 - r));
}
__device__ __forceinline__ void threefry2x32(uint32_t k0, uint32_t k1,
                                             uint32_t x0, uint32_t x1,
                                             uint32_t& o0, uint32_t& o1) {
    uint32_t ks2 = k0 ^ k1 ^ 0x1BD11BDAu;
    x0 += k0; x1 += k1;
#define TF_RND(r) { x0 += x1; x1 = rotl32(x1, (r)); x1 ^= x0; }
    TF_RND(13) TF_RND(15) TF_RND(26) TF_RND(6)   x0 += k1;  x1 += ks2 + 1u;
    TF_RND(17) TF_RND(29) TF_RND(16) TF_RND(24)  x0 += ks2; x1 += k0 + 2u;
    TF_RND(13) TF_RND(15) TF_RND(26) TF_RND(6)   x0 += k0;  x1 += k1 + 3u;
    TF_RND(17) TF_RND(29) TF_RND(16) TF_RND(24)  x0 += k1;  x1 += ks2 + 4u;
    TF_RND(13) TF_RND(15) TF_RND(26) TF_RND(6)   x0 += ks2; x1 += k0 + 5u;
#undef TF_RND
    o0 = x0; o1 = x1;
}
// start index for batch b (JAX threefry_partitionable=True path)
__device__ __forceinline__ int jax_start_idx(int b) {
    uint32_t k2a, k2b;
    threefry2x32(0u, 42u, 0u, 1u, k2a, k2b);
    uint32_t o0, o1;
    threefry2x32(k2a, k2b, 0u, (uint32_t)b, o0, o1);
    return (int)((o0 ^ o1) & (uint32_t)(N_PTS - 1));
}

// ---------------- cluster DSMEM / mbarrier / smem-sync helpers ----------------
__device__ __forceinline__ uint32_t mapa_peer(uint32_t laddr, uint32_t peer) {
    uint32_t r;
    asm volatile("mapa.shared::cluster.u32 %0, %1, %2;" : "=r"(r) : "r"(laddr), "r"(peer));
    return r;
}
__device__ __forceinline__ void st_async_raw_v4(uint32_t raddr, uint32_t rmbar,
                                                uint32_t a, uint32_t b,
                                                uint32_t c, uint32_t d) {
    asm volatile("st.async.shared::cluster.mbarrier::complete_tx::bytes.v4.b32 "
                 "[%0], {%1,%2,%3,%4}, [%5];"
                 :: "r"(raddr), "r"(a), "r"(b), "r"(c), "r"(d), "r"(rmbar) : "memory");
}
__device__ __forceinline__ void mbar_expect_tx(uint32_t mbar, uint32_t bytes) {
    asm volatile("mbarrier.arrive.expect_tx.shared.b64 _, [%0], %1;"
                 :: "r"(mbar), "r"(bytes) : "memory");
}
__device__ __forceinline__ void mbar_wait(uint32_t mbar, uint32_t phase) {
    uint32_t done = 0;
    while (!done) {
        asm volatile(
            "{\n\t.reg .pred p;\n\t"
            "mbarrier.try_wait.parity.acquire.cluster.shared::cta.b64 p, [%1], %2, 0x989680;\n\t"
            "selp.b32 %0, 1, 0, p;\n\t}"
            : "=r"(done) : "r"(mbar), "r"(phase) : "memory");
    }
}
__device__ __forceinline__ uint32_t ld_acquire_cta(uint32_t addr) {
    uint32_t v;
    asm volatile("ld.acquire.cta.shared::cta.b32 %0, [%1];" : "=r"(v) : "r"(addr) : "memory");
    return v;
}
__device__ __forceinline__ void st_release_cta(uint32_t addr, uint32_t v) {
    asm volatile("st.release.cta.shared::cta.b32 [%0], %1;" :: "r"(addr), "r"(v) : "memory");
}

// ---------------- fused FPS + ball + gather: one 8-CTA cluster per batch ----
// BLOCKED mapping (fps threads): fps-thread ft owns indices
//   [rank*2048 + ft*PPT, rank*2048 + (ft+1)*PPT)  -> index order == slot order,
// so every tie-break is ffs(ballot) and no index is ever transported.
__global__ void __cluster_dims__(CL, 1, 1) __launch_bounds__(TPB, 1)
fused_kernel(const float* __restrict__ xyz, const float* __restrict__ feat,
             float* __restrict__ out_xyz, float* __restrict__ out_feat) {
    const int b = blockIdx.x / CL;
    uint32_t rank;
    asm("mov.u32 %0, %%cluster_ctarank;" : "=r"(rank));
    const float* __restrict__ X = xyz + (size_t)b * N_PTS * 3;
    const int t = threadIdx.x;
    const int lane = t & 31, w = t >> 5;

    __shared__ uint4 s_q[2][NSLOT];          // cross-CTA candidates, dbl-buffered
    __shared__ unsigned long long s_mbar[2];
    __shared__ float4 s_ring[N_SAMP];        // published samples (x,y,z)
    __shared__ int    s_nb[NWARP_FPS][K_NEI];// per-ball-warp neighbor list
    __shared__ uint32_t s_cnt;               // samples available

    if (t == 0) {
        asm volatile("mbarrier.init.shared.b64 [%0], %1;"
                     :: "r"((uint32_t)__cvta_generic_to_shared(&s_mbar[0])), "r"(1) : "memory");
        asm volatile("mbarrier.init.shared.b64 [%0], %1;"
                     :: "r"((uint32_t)__cvta_generic_to_shared(&s_mbar[1])), "r"(1) : "memory");
        s_cnt = 0u;
    }
    __syncthreads();
    asm volatile("barrier.cluster.arrive.aligned;" ::: "memory");
    asm volatile("barrier.cluster.wait.aligned;" ::: "memory");

    const uint32_t cnt_addr = (uint32_t)__cvta_generic_to_shared(&s_cnt);

    if (w >= NWARP_FPS) {
        // ================= FPS warps (4-7; higher wid -> arbiter priority) ====
        const int ft = t - 128;                       // fps thread id 0..127
        const int wf = w - NWARP_FPS;                 // fps warp 0..3
        const int tbase = (int)rank * 2048 + ft * PPT;

        float px[PPT], py[PPT], pz[PPT], md[PPT];
#pragma unroll
        for (int j = 0; j < PPT; j++) {
            const float* a = X + 3 * (tbase + j);
            px[j] = a[0]; py[j] = a[1]; pz[j] = a[2];
            md[j] = __int_as_float(0x7f800000);       // +inf
        }
        uint64_t px2[NPAIR], py2[NPAIR], pz2[NPAIR];
#pragma unroll
        for (int p = 0; p < NPAIR; p++) {
            px2[p] = pack2(px[2 * p], px[2 * p + 1]);
            py2[p] = pack2(py[2 * p], py[2 * p + 1]);
            pz2[p] = pack2(pz[2 * p], pz[2 * p + 1]);
        }

        // pre-resolve remote slot/mbar addresses for my warp's slot, both buffers
        const int myslot = (int)rank * NWARP_FPS + wf;
        uint32_t rs0[CL], rs1[CL], rm0[CL], rm1[CL];
        {
            uint32_t a0 = (uint32_t)__cvta_generic_to_shared(&s_q[0][myslot]);
            uint32_t a1 = (uint32_t)__cvta_generic_to_shared(&s_q[1][myslot]);
            uint32_t m0 = (uint32_t)__cvta_generic_to_shared(&s_mbar[0]);
            uint32_t m1 = (uint32_t)__cvta_generic_to_shared(&s_mbar[1]);
#pragma unroll
            for (int p = 0; p < CL; p++) {
                rs0[p] = mapa_peer(a0, (uint32_t)p);
                rs1[p] = mapa_peer(a1, (uint32_t)p);
                rm0[p] = mapa_peer(m0, (uint32_t)p);
                rm1[p] = mapa_peer(m1, (uint32_t)p);
            }
        }

        int cur = jax_start_idx(b);
        float qx = X[3 * cur + 0], qy = X[3 * cur + 1], qz = X[3 * cur + 2];
        if (t == 128) {   // publish sample 0 to local ball warps
            s_ring[0] = make_float4(qx, qy, qz, 0.f);
            st_release_cta(cnt_addr, 1u);
        }

        for (int s = 0; ; s++) {
            if (rank == 0 && t == 128) {
                float* o = out_xyz + ((size_t)b * N_SAMP + s) * 3;
                o[0] = qx; o[1] = qy; o[2] = qz;
            }
            if (s == N_SAMP - 1) break;

            const int buf = s & 1;
            if (t == 128)
                mbar_expect_tx((uint32_t)__cvta_generic_to_shared(&s_mbar[buf]), TX_BYTES);

            // ---- distance stage: packed f32x2 (EXACT: a-b==a+(-b), .rn, left-assoc) ----
            const uint64_t nqx2 = pack2(-qx, -qx);
            const uint64_t nqy2 = pack2(-qy, -qy);
            const uint64_t nqz2 = pack2(-qz, -qz);
            float m[PPT];
#pragma unroll
            for (int p = 0; p < NPAIR; p++) {
                uint64_t dx2 = add2(px2[p], nqx2);
                uint64_t dy2 = add2(py2[p], nqy2);
                uint64_t dz2 = add2(pz2[p], nqz2);
                uint64_t d2p = add2(add2(mul2(dx2, dx2), mul2(dy2, dy2)),
                                    mul2(dz2, dz2));
                float dlo, dhi;
                unpack2(d2p, dlo, dhi);
                float m0v = fminf(md[2 * p],     dlo);
                float m1v = fminf(md[2 * p + 1], dhi);
                md[2 * p] = m0v;  md[2 * p + 1] = m1v;
                m[2 * p]  = m0v;  m[2 * p + 1]  = m1v;
            }
            // ---- depth-4 argmax tree (left-priority => smallest j on ties) ----
            float tv[8], tx[8], ty[8], tz[8];
#pragma unroll
            for (int k = 0; k < 8; k++) {
                bool g = m[2 * k + 1] > m[2 * k];
                tv[k] = g ? m[2 * k + 1]  : m[2 * k];
                tx[k] = g ? px[2 * k + 1] : px[2 * k];
                ty[k] = g ? py[2 * k + 1] : py[2 * k];
                tz[k] = g ? pz[2 * k + 1] : pz[2 * k];
            }
#pragma unroll
            for (int n = 4; n >= 1; n >>= 1) {
#pragma unroll
                for (int k = 0; k < n; k++) {
                    bool g = tv[2 * k + 1] > tv[2 * k];
                    tv[k] = g ? tv[2 * k + 1] : tv[2 * k];
                    tx[k] = g ? tx[2 * k + 1] : tx[2 * k];
                    ty[k] = g ? ty[2 * k + 1] : ty[2 * k];
                    tz[k] = g ? tz[2 * k + 1] : tz[2 * k];
                }
            }
            const uint32_t bu = __float_as_uint(tv[0]);  // >=0: IEEE == u32 order

            // ---- warp argmax; winning lane broadcasts to all 8 CTAs ----
            uint32_t wm = __reduce_max_sync(FULL, bu);
            uint32_t mk = __ballot_sync(FULL, bu == wm);
            if (lane == __ffs(mk) - 1) {
                uint32_t cx = __float_as_uint(tx[0]);
                uint32_t cy = __float_as_uint(ty[0]);
                uint32_t cz = __float_as_uint(tz[0]);
                if (buf) {
#pragma unroll
                    for (int p = 0; p < CL; p++)
                        st_async_raw_v4(rs1[p], rm1[p], wm, cx, cy, cz);
                } else {
#pragma unroll
                    for (int p = 0; p < CL; p++)
                        st_async_raw_v4(rs0[p], rm0[p], wm, cx, cy, cz);
                }
            }

            // ---- wait + 1-slot-per-lane reduce; lowest winning slot wins ----
            mbar_wait((uint32_t)__cvta_generic_to_shared(&s_mbar[buf]),
                      (uint32_t)((s >> 1) & 1));
            uint4 dv = s_q[buf][lane];
            uint32_t gm = __reduce_max_sync(FULL, dv.x);
            uint32_t mk2 = __ballot_sync(FULL, dv.x == gm);
            int ws = __ffs(mk2) - 1;
            qx = __uint_as_float(__shfl_sync(FULL, dv.y, ws));
            qy = __uint_as_float(__shfl_sync(FULL, dv.z, ws));
            qz = __uint_as_float(__shfl_sync(FULL, dv.w, ws));

            if (t == 128) {  // publish sample s+1 (off the critical recurrence)
                s_ring[s + 1] = make_float4(qx, qy, qz, 0.f);
                st_release_cta(cnt_addr, (uint32_t)(s + 2));
            }
        }
    } else {
        // ================= ball+gather warps (0-3) ===========================
        const int wid32 = (int)rank * NWARP_FPS + w;   // 0..31 within batch
        const float4* __restrict__ F4 =
            (const float4*)(feat + (size_t)b * N_PTS * C_FEAT);
        const float R2 = 0.04f;  // f32(0.04): JAX weak-typed radius*radius
        for (int k = 0; k < N_SAMP / 32; k++) {
            const int s = k * 32 + wid32;
            while ((int)ld_acquire_cta(cnt_addr) <= s) __nanosleep(64);
            float4 q = s_ring[s];

            s_nb[w][lane] = -1;
            __syncwarp();
            int found = 0;
            for (int base = 0; base < N_PTS && found < K_NEI; base += 128) {
                float xs[4], ys[4], zs[4];
#pragma unroll
                for (int g = 0; g < 4; g++) {        // 12 LDGs in flight (MLP)
                    const float* a = X + 3 * (base + g * 32 + lane);
                    xs[g] = a[0]; ys[g] = a[1]; zs[g] = a[2];
                }
#pragma unroll
                for (int g = 0; g < 4; g++) {        // index-ordered groups
                    float dx = __fsub_rn(q.x, xs[g]);
                    float dy = __fsub_rn(q.y, ys[g]);
                    float dz = __fsub_rn(q.z, zs[g]);
                    float d2 = __fadd_rn(__fadd_rn(__fmul_rn(dx, dx),
                                                   __fmul_rn(dy, dy)),
                                         __fmul_rn(dz, dz));
                    bool in = d2 < R2;
                    unsigned mask = __ballot_sync(FULL, in);
                    if (in) {
                        int r = found + __popc(mask & ((1u << lane) - 1u));
                        if (r < K_NEI) s_nb[w][r] = base + g * 32 + lane;
                    }
                    found += __popc(mask);
                }
            }
            __syncwarp();
            // gather 32 feature rows (512B each), 4 rows in flight
            float4* dst = (float4*)(out_feat +
                           (((size_t)b * N_SAMP + s) * K_NEI) * C_FEAT);
#pragma unroll 1
            for (int k2 = 0; k2 < K_NEI; k2 += 4) {
                int r0 = s_nb[w][k2 + 0]; r0 = (r0 < 0) ? N_SAMP : r0;
                int r1 = s_nb[w][k2 + 1]; r1 = (r1 < 0) ? N_SAMP : r1;
                int r2 = s_nb[w][k2 + 2]; r2 = (r2 < 0) ? N_SAMP : r2;
                int r3 = s_nb[w][k2 + 3]; r3 = (r3 < 0) ? N_SAMP : r3;
                float4 v0 = F4[(size_t)r0 * 32 + lane];
                float4 v1 = F4[(size_t)r1 * 32 + lane];
                float4 v2 = F4[(size_t)r2 * 32 + lane];
                float4 v3 = F4[(size_t)r3 * 32 + lane];
                dst[(size_t)(k2 + 0) * 32 + lane] = v0;
                dst[(size_t)(k2 + 1) * 32 + lane] = v1;
                dst[(size_t)(k2 + 2) * 32 + lane] = v2;
                dst[(size_t)(k2 + 3) * 32 + lane] = v3;
            }
        }
    }

    // drain: no CTA exits while peers may still target its smem
    asm volatile("barrier.cluster.arrive.aligned;" ::: "memory");
    asm volatile("barrier.cluster.wait.aligned;" ::: "memory");
}

extern "C" void kernel_launch(void* const* d_in, const int* in_sizes, int n_in,
                              void* d_out, int out_size) {
    const float* xyz  = (const float*)d_in[0];
    const float* feat = (const float*)d_in[1];
    if (n_in >= 2 && in_sizes[0] != BATCH * N_PTS * 3) {  // defensive: by size
        xyz  = (const float*)d_in[1];
        feat = (const float*)d_in[0];
    }
    float* out = (float*)d_out;
    float* out_feat = out + (size_t)BATCH * N_SAMP * 3;

    fused_kernel<<<BATCH * CL, TPB>>>(xyz, feat, out, out_feat);
}